// round 3
// baseline (speedup 1.0000x reference)
#include <cuda_runtime.h>
#include <math.h>

#define NC   19
#define NIMG 4
#define HWN  (768*768)          // 589824 pixels per image
#define TOTAL_PIX (NIMG*HWN)    // 2359296

// ---------------- device scratch (no allocations allowed) ----------------
__device__ unsigned int g_hist_seg[NIMG][NC];
__device__ unsigned int g_hist_att[NIMG][NC];
__device__ unsigned long long g_pos_cnt;
__device__ unsigned long long g_neg_cnt;
__device__ double g_bce_pos;
__device__ double g_bce_neg;
__device__ float  g_coefA[NIMG][NC];   // w_seg / den_seg
__device__ float  g_coefB[NIMG][NC];   // 0.1 * w_att / den_att
__device__ double g_accum;             // sum of coef * logp   (negative)
__device__ double g_edge_term;         // 0.3 * weighted-mean BCE

__device__ __forceinline__ float warp_sum_f(float x) {
#pragma unroll
    for (int o = 16; o > 0; o >>= 1) x += __shfl_down_sync(0xffffffffu, x, o);
    return x;
}
__device__ __forceinline__ unsigned warp_sum_u(unsigned x) {
#pragma unroll
    for (int o = 16; o > 0; o >>= 1) x += __shfl_down_sync(0xffffffffu, x, o);
    return x;
}

// ---------------- kernel 0: zero scratch ----------------
__global__ void init_kernel() {
    int t = threadIdx.x;
    if (t < NIMG * NC) {
        ((unsigned int*)g_hist_seg)[t] = 0u;
        ((unsigned int*)g_hist_att)[t] = 0u;
    }
    if (t == 0) {
        g_pos_cnt = 0ull; g_neg_cnt = 0ull;
        g_bce_pos = 0.0;  g_bce_neg = 0.0;
        g_accum = 0.0;    g_edge_term = 0.0;
    }
}

// ---------------- kernel 1: histograms + BCE partials ----------------
// grid = (256, NIMG), block = 256. Each thread handles exactly 9 pixels.
__global__ void __launch_bounds__(256) stats_kernel(
        const float* __restrict__ edgein,
        const int*   __restrict__ segmask,
        const int*   __restrict__ edgemask) {
    const int n    = blockIdx.y;
    const int tid  = threadIdx.x;
    const int lane = tid & 31;
    const int warp = tid >> 5;
    const size_t base = (size_t)n * HWN;
    const int gid = blockIdx.x * 256 + tid;      // [0, 65536)

    __shared__ unsigned int sh_seg[NC];
    __shared__ unsigned int sh_att[NC];
    __shared__ float sh_bp[8], sh_bn[8];
    __shared__ unsigned sh_p[8], sh_q[8];

    if (tid < NC) { sh_seg[tid] = 0u; sh_att[tid] = 0u; }
    __syncthreads();

    unsigned cseg = 0, catt = 0;       // lane c (<NC) owns class c
    float bp = 0.f, bn = 0.f;
    unsigned p = 0, q = 0;

#pragma unroll 1
    for (int k = 0; k < 9; k++) {
        int i = k * 65536 + gid;                   // < HWN exactly
        int   t  = segmask[base + i];
        float e  = edgein [base + i];
        int   em = edgemask[base + i];
        bool inb = ((unsigned)t < (unsigned)NC);
        bool att = inb && (e > 0.8f);
        unsigned batt = __ballot_sync(0xffffffffu, att);
#pragma unroll
        for (int c = 0; c < NC; c++) {
            unsigned bs = __ballot_sync(0xffffffffu, inb && (t == c));
            if (lane == c) {
                cseg += __popc(bs);
                catt += __popc(bs & batt);
            }
        }
        // stable BCE with logits, target = em (0/1)
        float bce = fmaxf(e, 0.f) - e * (float)em + log1pf(__expf(-fabsf(e)));
        if (em == 1)      { bp += bce; p++; }
        else if (em == 0) { bn += bce; q++; }
    }

    // merge per-warp class counts into shared
    if (lane < NC) {
        atomicAdd(&sh_seg[lane], cseg);
        atomicAdd(&sh_att[lane], catt);
    }
    // reduce bce / counts
    bp = warp_sum_f(bp); bn = warp_sum_f(bn);
    p  = warp_sum_u(p);  q  = warp_sum_u(q);
    if (lane == 0) { sh_bp[warp] = bp; sh_bn[warp] = bn; sh_p[warp] = p; sh_q[warp] = q; }
    __syncthreads();

    if (tid < NC) {
        atomicAdd(&g_hist_seg[n][tid], sh_seg[tid]);
        atomicAdd(&g_hist_att[n][tid], sh_att[tid]);
    }
    if (tid == 0) {
        float tbp = 0.f, tbn = 0.f; unsigned tp = 0, tq = 0;
#pragma unroll
        for (int w = 0; w < 8; w++) { tbp += sh_bp[w]; tbn += sh_bn[w]; tp += sh_p[w]; tq += sh_q[w]; }
        atomicAdd(&g_bce_pos, (double)tbp);
        atomicAdd(&g_bce_neg, (double)tbn);
        atomicAdd(&g_pos_cnt, (unsigned long long)tp);
        atomicAdd(&g_neg_cnt, (unsigned long long)tq);
    }
}

// ---------------- kernel 2: fold histograms into coefficients ----------------
__global__ void weights_kernel() {
    const int tid = threadIdx.x;                  // 128 threads, 1 block
    __shared__ double wseg[NIMG][NC], watt[NIMG][NC];
    __shared__ double den_seg[NIMG], den_att[NIMG];

    if (tid < NIMG * NC) {
        int n = tid / NC, c = tid % NC;
        double tot_s = 0.0, tot_a = 0.0;
        for (int cc = 0; cc < NC; cc++) {
            tot_s += (double)g_hist_seg[n][cc];
            tot_a += (double)g_hist_att[n][cc];
        }
        double bs = (double)g_hist_seg[n][c];
        double ba = (double)g_hist_att[n][c];
        // w = (bins != 0) * 1.0 * (1 - bins/total) + 1.0
        wseg[n][c] = (bs != 0.0 ? (1.0 - bs / tot_s) : 0.0) + 1.0;
        watt[n][c] = (ba != 0.0 ? (1.0 - ba / tot_a) : 0.0) + 1.0;
    }
    __syncthreads();
    if (tid < NIMG) {
        double ds = 0.0, da = 0.0;
        for (int c = 0; c < NC; c++) {
            ds += (double)g_hist_seg[tid][c] * wseg[tid][c];
            da += (double)g_hist_att[tid][c] * watt[tid][c];
        }
        den_seg[tid] = ds; den_att[tid] = da;
    }
    __syncthreads();
    if (tid < NIMG * NC) {
        int n = tid / NC, c = tid % NC;
        g_coefA[n][c] = (float)(wseg[n][c] / den_seg[n]);
        g_coefB[n][c] = (float)(0.1 * watt[n][c] / den_att[n]);
    }
    if (tid == 0) {
        double pos = (double)g_pos_cnt, neg = (double)g_neg_cnt;
        double s = pos + neg;
        double wsum = (neg / s) * g_bce_pos + (pos / s) * g_bce_neg;
        g_edge_term = 0.3 * wsum / (double)TOTAL_PIX;
    }
}

// ---------------- kernel 3: main pass over segin (the big one) ----------------
// grid = (2304, NIMG), block = 256 : one pixel per thread, no remainder.
__global__ void __launch_bounds__(256) main_kernel(
        const float* __restrict__ segin,
        const float* __restrict__ edgein,
        const int*   __restrict__ segmask) {
    const int n   = blockIdx.y;
    const int pix = blockIdx.x * 256 + threadIdx.x;   // < HWN exactly
    const size_t pb = (size_t)n * HWN + pix;

    __shared__ float shA[NC], shB[NC];
    if (threadIdx.x < NC) {
        shA[threadIdx.x] = g_coefA[n][threadIdx.x];
        shB[threadIdx.x] = g_coefB[n][threadIdx.x];
    }
    __syncthreads();

    int t = segmask[pb];
    t = min(max(t, 0), NC - 1);
    float e = edgein[pb];
    const float* sp = segin + (size_t)n * NC * HWN + pix;

    float v[NC];
#pragma unroll
    for (int c = 0; c < NC; c++) v[c] = __ldg(sp + (size_t)c * HWN);

    float m = v[0];
#pragma unroll
    for (int c = 1; c < NC; c++) m = fmaxf(m, v[c]);

    float s = 0.f, vt = v[0];
#pragma unroll
    for (int c = 0; c < NC; c++) {
        s += __expf(v[c] - m);
        if (c == t) vt = v[c];      // static index -> predicated select, no spills
    }
    float lp = vt - m - __logf(s);                 // log p(target)
    float coeff = shA[t] + ((e > 0.8f) ? shB[t] : 0.f);
    float contrib = coeff * lp;

    // block reduction -> one double atomic per block
    __shared__ float sh_red[8];
    contrib = warp_sum_f(contrib);
    if ((threadIdx.x & 31) == 0) sh_red[threadIdx.x >> 5] = contrib;
    __syncthreads();
    if (threadIdx.x == 0) {
        float bsum = 0.f;
#pragma unroll
        for (int w = 0; w < 8; w++) bsum += sh_red[w];
        atomicAdd(&g_accum, (double)bsum);
    }
}

// ---------------- kernel 4: final scalar ----------------
__global__ void final_kernel(float* out) {
    // seg_loss + att_loss = -accum   (coefficients already carry 1.0 and 0.1)
    out[0] = (float)(-g_accum + g_edge_term);
}

// ---------------- launch ----------------
extern "C" void kernel_launch(void* const* d_in, const int* in_sizes, int n_in,
                              void* d_out, int out_size) {
    const float* segin    = (const float*)d_in[0];   // [4,19,768,768] f32
    const float* edgein   = (const float*)d_in[1];   // [4,1,768,768]  f32
    const int*   segmask  = (const int*)  d_in[2];   // [4,768,768]    i32
    const int*   edgemask = (const int*)  d_in[3];   // [4,1,768,768]  i32
    float* out = (float*)d_out;

    init_kernel<<<1, 256>>>();
    stats_kernel<<<dim3(256, NIMG), 256>>>(edgein, segmask, edgemask);
    weights_kernel<<<1, 128>>>();
    main_kernel<<<dim3(HWN / 256, NIMG), 256>>>(segin, edgein, segmask);
    final_kernel<<<1, 1>>>(out);
}

// round 4
// speedup vs baseline: 1.2936x; 1.2936x over previous
#include <cuda_runtime.h>
#include <math.h>

#define NC        19
#define NIMG      4
#define HWN       589824          // 768*768
#define TOTAL_PIX 2359296         // NIMG*HWN
#define GRID      576
#define BLK       256
#define NTHREADS  147456          // GRID*BLK
#define PPT       16              // pixels per thread (TOTAL_PIX / NTHREADS exactly)

// ---------------- device scratch (static, no allocations) ----------------
// Invariant: every value below that is accumulated via atomics is re-zeroed by
// the reducer blocks at the END of each run, so each launch (incl. graph
// replays) starts from zero. g_bar is monotonic and never reset.
__device__ unsigned long long g_bar;                 // grid-barrier ticket counter
__device__ unsigned int g_hist[NIMG][2][NC];         // [img][seg|att][class]
__device__ double g_bce[2];                          // pos,neg BCE sums
__device__ unsigned int g_cnt[2];                    // pos,neg counts
__device__ float  g_coefA[NIMG][NC];                 // w_seg / den_seg     (overwritten)
__device__ float  g_coefB[NIMG][NC];                 // 0.1*w_att/den_att   (overwritten)
__device__ double g_edge;                            // 0.3*weighted BCE    (overwritten)
__device__ double g_accum;                           // sum coef*logp

__device__ __forceinline__ float warp_sum_f(float x) {
#pragma unroll
    for (int o = 16; o > 0; o >>= 1) x += __shfl_down_sync(0xffffffffu, x, o);
    return x;
}
__device__ __forceinline__ unsigned warp_sum_u(unsigned x) {
#pragma unroll
    for (int o = 16; o > 0; o >>= 1) x += __shfl_down_sync(0xffffffffu, x, o);
    return x;
}

// release-arrive / acquire-spin grid barrier; replay-safe (monotonic counter).
__device__ __forceinline__ void bar_arrive_wait() {
    __syncthreads();
    if (threadIdx.x == 0) {
        unsigned long long r;
        asm volatile("atom.release.gpu.global.add.u64 %0, [%1], 1;"
                     : "=l"(r) : "l"(&g_bar) : "memory");
        unsigned long long target = (r / GRID + 1ull) * (unsigned long long)GRID;
        unsigned long long v;
        do {
            asm volatile("ld.acquire.gpu.global.u64 %0, [%1];"
                         : "=l"(v) : "l"(&g_bar) : "memory");
        } while (v < target);
    }
    __syncthreads();
}
__device__ __forceinline__ unsigned long long bar_arrive_only() {
    __syncthreads();
    unsigned long long r = 0;
    if (threadIdx.x == 0) {
        asm volatile("atom.release.gpu.global.add.u64 %0, [%1], 1;"
                     : "=l"(r) : "l"(&g_bar) : "memory");
    }
    return r;
}

__global__ void __launch_bounds__(BLK, 4) fused_kernel(
        const float* __restrict__ segin,
        const float* __restrict__ edgein,
        const int*   __restrict__ segmask,
        const int*   __restrict__ edgemask,
        float* __restrict__ out) {
    const int tid  = threadIdx.x;
    const int lane = tid & 31;
    const int warp = tid >> 5;
    const int idx0 = blockIdx.x * BLK + tid;         // [0, NTHREADS)

    __shared__ unsigned sh_hist[NIMG * 2 * NC];      // 152 counters
    __shared__ float    sh_bp[8], sh_bn[8];
    __shared__ unsigned sh_cp[8], sh_cn[8];
    __shared__ float    shA[NIMG * NC], shB[NIMG * NC];
    __shared__ float    sh_red[8];

    // ---------------- phase 1: histograms + BCE + per-pixel pack ----------------
    for (int j = tid; j < NIMG * 2 * NC; j += BLK) sh_hist[j] = 0u;
    __syncthreads();

    unsigned long long p0 = 0ull, p1 = 0ull;         // 16 packed bytes in regs
    float bp = 0.f, bn = 0.f;
    unsigned cp = 0u, cn = 0u;

#pragma unroll
    for (int k = 0; k < PPT; k++) {
        const int n = k >> 2;                        // image index (HWN/NTHREADS == 4)
        const size_t idx = (size_t)idx0 + (size_t)k * NTHREADS;
        int   t  = segmask[idx];
        float e  = edgein [idx];
        int   em = edgemask[idx];

        bool inb = ((unsigned)t < (unsigned)NC);     // histogram membership
        bool vs  = (t != 255);                       // seg-valid
        bool att = (e > 0.8f);
        bool va  = vs && att;                        // att-valid
        int  tc  = min(max(t, 0), NC - 1);

        if (inb) {
            atomicAdd(&sh_hist[(n * 2 + 0) * NC + t], 1u);
            if (att) atomicAdd(&sh_hist[(n * 2 + 1) * NC + t], 1u);
        }
        unsigned byte = (unsigned)tc | (vs ? 32u : 0u) | (va ? 64u : 0u);
        if (k < 8) p0 |= (unsigned long long)byte << (8 * k);
        else       p1 |= (unsigned long long)byte << (8 * (k - 8));

        float bce = fmaxf(e, 0.f) - e * (float)em + log1pf(__expf(-fabsf(e)));
        if (em == 1)      { bp += bce; cp++; }
        else if (em == 0) { bn += bce; cn++; }
    }

    bp = warp_sum_f(bp); bn = warp_sum_f(bn);
    cp = warp_sum_u(cp); cn = warp_sum_u(cn);
    if (lane == 0) { sh_bp[warp] = bp; sh_bn[warp] = bn; sh_cp[warp] = cp; sh_cn[warp] = cn; }
    __syncthreads();

    if (tid < NIMG * 2 * NC) {
        unsigned v = sh_hist[tid];
        if (v) atomicAdd(&((unsigned*)g_hist)[tid], v);
    }
    if (tid == 0) {
        float tbp = 0.f, tbn = 0.f; unsigned tcp = 0, tcn = 0;
#pragma unroll
        for (int w = 0; w < 8; w++) { tbp += sh_bp[w]; tbn += sh_bn[w]; tcp += sh_cp[w]; tcn += sh_cn[w]; }
        atomicAdd(&g_bce[0], (double)tbp);
        atomicAdd(&g_bce[1], (double)tbn);
        atomicAdd(&g_cnt[0], tcp);
        atomicAdd(&g_cnt[1], tcn);
    }

    bar_arrive_wait();   // ---- barrier 1: all stats in g_hist / g_bce / g_cnt ----

    // ---------------- phase 2: reducer blocks compute coefficients ----------------
    if (blockIdx.x < NIMG) {
        const int n = blockIdx.x;
        __shared__ double sw[2 * NC];
        __shared__ double sden[2];
        if (tid < 2 * NC) {
            int which = tid / NC, c = tid % NC;
            double tot = 0.0;
            for (int cc = 0; cc < NC; cc++) tot += (double)g_hist[n][which][cc];
            double b = (double)g_hist[n][which][c];
            sw[which * NC + c] = (b != 0.0 ? (1.0 - b / tot) : 0.0) + 1.0;
        }
        __syncthreads();
        if (tid < 2) {
            double d = 0.0;
            for (int c = 0; c < NC; c++) d += (double)g_hist[n][tid][c] * sw[tid * NC + c];
            sden[tid] = d;
        }
        __syncthreads();
        if (tid < NC) {
            g_coefA[n][tid] = (float)(sw[tid] / sden[0]);
            g_coefB[n][tid] = (float)(0.1 * sw[NC + tid] / sden[1]);
        }
        __syncthreads();
        if (tid < 2 * NC) g_hist[n][tid / NC][tid % NC] = 0u;   // re-zero for next replay
    } else if (blockIdx.x == NIMG && tid == 0) {
        double pos = (double)g_cnt[0], neg = (double)g_cnt[1];
        double s = pos + neg;
        g_edge = 0.3 * ((neg / s) * g_bce[0] + (pos / s) * g_bce[1]) / (double)TOTAL_PIX;
        g_bce[0] = 0.0; g_bce[1] = 0.0; g_cnt[0] = 0u; g_cnt[1] = 0u;
    }

    bar_arrive_wait();   // ---- barrier 2: coefficients + edge term published ----

    // ---------------- phase 3: single pass over segin ----------------
    if (tid < NIMG * NC) {
        shA[tid] = ((const float*)g_coefA)[tid];
        shB[tid] = ((const float*)g_coefB)[tid];
    }
    __syncthreads();

    float acc = 0.f;
#pragma unroll 1
    for (int k = 0; k < PPT; k++) {
        const int n = k >> 2;
        const unsigned long long src = (k < 8) ? p0 : p1;
        const unsigned byte = (unsigned)(src >> ((k & 7) * 8)) & 0xffu;
        const int t = (int)(byte & 31u);
        const size_t i = (size_t)idx0 + (size_t)(k & 3) * NTHREADS;  // pixel within image
        const float* sp = segin + (size_t)n * (NC * (size_t)HWN) + i;

        float v[NC];
#pragma unroll
        for (int c = 0; c < NC; c++) v[c] = __ldg(sp + (size_t)c * HWN);

        float m = v[0];
#pragma unroll
        for (int c = 1; c < NC; c++) m = fmaxf(m, v[c]);

        float s = 0.f, vt = v[0];
#pragma unroll
        for (int c = 0; c < NC; c++) {
            s += __expf(v[c] - m);
            if (c == t) vt = v[c];
        }
        float lp = vt - m - __logf(s);
        float coeff = ((byte & 32u) ? shA[n * NC + t] : 0.f)
                    + ((byte & 64u) ? shB[n * NC + t] : 0.f);
        acc += coeff * lp;
    }

    acc = warp_sum_f(acc);
    if (lane == 0) sh_red[warp] = acc;
    __syncthreads();
    if (tid == 0) {
        float bsum = 0.f;
#pragma unroll
        for (int w = 0; w < 8; w++) bsum += sh_red[w];
        atomicAdd(&g_accum, (double)bsum);
    }

    // ---- barrier 3: arrive-only; block 0 waits and finalizes ----
    if (blockIdx.x == 0) {
        __syncthreads();
        if (tid == 0) {
            unsigned long long r;
            asm volatile("atom.release.gpu.global.add.u64 %0, [%1], 1;"
                         : "=l"(r) : "l"(&g_bar) : "memory");
            unsigned long long target = (r / GRID + 1ull) * (unsigned long long)GRID;
            unsigned long long v;
            do {
                asm volatile("ld.acquire.gpu.global.u64 %0, [%1];"
                             : "=l"(v) : "l"(&g_bar) : "memory");
            } while (v < target);
            double a = atomicAdd(&g_accum, 0.0);     // coherent read
            out[0] = (float)(-a + g_edge);
            g_accum = 0.0;                            // re-zero for next replay
        }
    } else {
        bar_arrive_only();
    }
}

// ---------------- launch ----------------
extern "C" void kernel_launch(void* const* d_in, const int* in_sizes, int n_in,
                              void* d_out, int out_size) {
    const float* segin    = (const float*)d_in[0];   // [4,19,768,768] f32
    const float* edgein   = (const float*)d_in[1];   // [4,1,768,768]  f32
    const int*   segmask  = (const int*)  d_in[2];   // [4,768,768]    i32
    const int*   edgemask = (const int*)  d_in[3];   // [4,1,768,768]  i32
    float* out = (float*)d_out;

    fused_kernel<<<GRID, BLK>>>(segin, edgein, segmask, edgemask, out);
}